// round 11
// baseline (speedup 1.0000x reference)
#include <cuda_runtime.h>
#include <cuda_fp16.h>
#include <cstdint>

#define S_LEN   2048
#define D_K     64
#define BH      64
#define MT      64
#define NT      64
#define PQ2     36    // half2 pad: Qh/Ph reads banks 4g+tig -> conflict-free
#define PKV2    72    // half2 pad: Kt/Vt reads banks 8tig+g -> conflict-free
#define THREADS 256
#define NBLOCKS (BH * (S_LEN / MT))   // 2048

__device__ float g_linv[BH * S_LEN];
__device__ int   g_queue[NBLOCKS];
__device__ int   g_push;
__device__ int   g_ticket;
// fp16 unnormalized attn scratch (536 MB static; consumer expands to fp32)
__device__ half2 g_pattn[(size_t)BH * S_LEN * (S_LEN / 2)];

__device__ __forceinline__ uint32_t pack_h2(float lo, float hi) {
    half2 h = __floats2half2_rn(lo, hi);
    return *(uint32_t*)&h;
}

__device__ __forceinline__ void mma_f16(float c[4],
                                        uint32_t a0, uint32_t a1, uint32_t a2, uint32_t a3,
                                        uint32_t b0, uint32_t b1) {
    asm volatile(
        "mma.sync.aligned.m16n8k16.row.col.f32.f16.f16.f32 "
        "{%0,%1,%2,%3},{%4,%5,%6,%7},{%8,%9},{%0,%1,%2,%3};"
        : "+f"(c[0]), "+f"(c[1]), "+f"(c[2]), "+f"(c[3])
        : "r"(a0), "r"(a1), "r"(a2), "r"(a3), "r"(b0), "r"(b1));
}

__global__ __launch_bounds__(THREADS, 3)
void sdpa_fused(const float* __restrict__ Q, const float* __restrict__ K,
                const float* __restrict__ V, const int* __restrict__ mask,
                float* __restrict__ out) {
    extern __shared__ char smraw[];
    half2* Qh = (half2*)smraw;               // 64 x PQ2  (row, k2)
    half2* Ph = Qh + MT * PQ2;               // 64 x PQ2  (row, k2)
    half2* Kt = Ph + MT * PQ2;               // 32 x PKV2 (k2, key)
    half2* Vt = Kt + 32 * PKV2;              // 32 x PKV2 (k2, d)
    float* red = (float*)(Vt + 32 * PKV2);   // 64 x 4
    float* liS = red + MT * 4;               // 64
    __shared__ int s_strip;

    const int bh  = blockIdx.y;
    const int q0  = blockIdx.x * MT;
    const int myid = blockIdx.y * gridDim.x + blockIdx.x;
    const int tid = threadIdx.x;
    const int lane = tid & 31, wid = tid >> 5;
    const int g = lane >> 2, tig = lane & 3;
    const int wm = wid & 1;                  // 2 warps in M (32 rows each)
    const int wn = wid >> 1;                 // 4 warps in N (16 cols each)

    const float* Qg = Q + ((size_t)bh * S_LEN + q0) * D_K;
    const float* Kg = K + (size_t)bh * S_LEN * D_K;
    const float* Vg = V + (size_t)bh * S_LEN * D_K;
    const int*   Mg = mask + (size_t)bh * S_LEN * S_LEN;
    float* ctx  = out + (size_t)bh * S_LEN * D_K;
    float* attn_base = out + (size_t)BH * S_LEN * D_K;
    half*  pattn = (half*)g_pattn + (size_t)bh * S_LEN * S_LEN;

    // ---- Q -> fp16 smem (scale 1/8 folded) ----
    {
        const float4* q4 = (const float4*)Qg;
        #pragma unroll
        for (int i = 0; i < 4; i++) {
            int idx = i * THREADS + tid;
            float4 v = q4[idx];
            int row = idx >> 4;
            int c2  = (idx & 15) * 2;
            Qh[row * PQ2 + c2]     = __floats2half2_rn(v.x * 0.125f, v.y * 0.125f);
            Qh[row * PQ2 + c2 + 1] = __floats2half2_rn(v.z * 0.125f, v.w * 0.125f);
        }
    }

    // ---- preload K(0) into registers ----
    float4 kreg[4];
    #pragma unroll
    for (int i = 0; i < 4; i++) {
        int f = i * THREADS + tid;
        int key = f & 63, kb = f >> 6;
        kreg[i] = *(const float4*)(Kg + (size_t)key * D_K + kb * 4);
    }

    float o[2][2][4] = {};
    float lp[2][2] = {};

    for (int kt = 0; kt < S_LEN; kt += NT) {
        __syncthreads();                     // prev tile's smem consumers done

        // ---- K(t) STS from kreg (k2-major half2) ----
        #pragma unroll
        for (int i = 0; i < 4; i++) {
            int f = i * THREADS + tid;
            int key = f & 63, kb = f >> 6;
            Kt[(2 * kb)     * PKV2 + key] = __floats2half2_rn(kreg[i].x, kreg[i].y);
            Kt[(2 * kb + 1) * PKV2 + key] = __floats2half2_rn(kreg[i].z, kreg[i].w);
        }

        // ---- V(t) LDG (consumed after exp; long cover) ----
        float4 va[2], vb[2];
        {
            int dq = tid & 15;
            #pragma unroll
            for (int i2 = 0; i2 < 2; i2++) {
                int k2 = (tid >> 4) + 16 * i2;
                va[i2] = *(const float4*)(Vg + (size_t)(kt + 2 * k2)     * D_K + 4 * dq);
                vb[i2] = *(const float4*)(Vg + (size_t)(kt + 2 * k2 + 1) * D_K + 4 * dq);
            }
        }

        // ---- mask prefetch -> bitmask (overlaps QK) ----
        uint32_t mbits = 0;
        #pragma unroll
        for (int mb = 0; mb < 2; mb++) {
            int row = wm * 32 + mb * 16 + g;
            #pragma unroll
            for (int nf = 0; nf < 2; nf++) {
                int col = wn * 16 + nf * 8 + 2 * tig;
                int2 m0 = *(const int2*)(Mg + (size_t)(q0 + row)     * S_LEN + kt + col);
                int2 m1 = *(const int2*)(Mg + (size_t)(q0 + row + 8) * S_LEN + kt + col);
                int b = (mb * 2 + nf) * 4;
                mbits |= ((m0.x ? 1u : 0u) << b) | ((m0.y ? 2u : 0u) << b)
                       | ((m1.x ? 4u : 0u) << b) | ((m1.y ? 8u : 0u) << b);
            }
        }
        __syncthreads();                     // Kt visible

        // ---- S = Q K^T (fp16 mma, k16) ----
        float acc[2][2][4] = {};
        #pragma unroll
        for (int j = 0; j < 4; j++) {
            uint32_t a[2][4];
            #pragma unroll
            for (int mb = 0; mb < 2; mb++) {
                int r = wm * 32 + mb * 16 + g;
                a[mb][0] = *(uint32_t*)&Qh[r       * PQ2 + 8 * j + tig];
                a[mb][1] = *(uint32_t*)&Qh[(r + 8) * PQ2 + 8 * j + tig];
                a[mb][2] = *(uint32_t*)&Qh[r       * PQ2 + 8 * j + tig + 4];
                a[mb][3] = *(uint32_t*)&Qh[(r + 8) * PQ2 + 8 * j + tig + 4];
            }
            #pragma unroll
            for (int nf = 0; nf < 2; nf++) {
                int nc = wn * 16 + nf * 8 + g;
                uint32_t b0 = *(uint32_t*)&Kt[(8 * j + tig)     * PKV2 + nc];
                uint32_t b1 = *(uint32_t*)&Kt[(8 * j + tig + 4) * PKV2 + nc];
                #pragma unroll
                for (int mb = 0; mb < 2; mb++)
                    mma_f16(acc[mb][nf], a[mb][0], a[mb][1], a[mb][2], a[mb][3], b0, b1);
            }
        }

        // ---- p = mask*exp(s): fp16 global store, Ph store, row sums ----
        #pragma unroll
        for (int mb = 0; mb < 2; mb++) {
            int row = wm * 32 + mb * 16 + g;
            #pragma unroll
            for (int nf = 0; nf < 2; nf++) {
                int col = wn * 16 + nf * 8 + 2 * tig;
                int b = (mb * 2 + nf) * 4;
                float p00 = (mbits >> b & 1u) ? __expf(acc[mb][nf][0]) : 0.f;
                float p01 = (mbits >> b & 2u) ? __expf(acc[mb][nf][1]) : 0.f;
                float p10 = (mbits >> b & 4u) ? __expf(acc[mb][nf][2]) : 0.f;
                float p11 = (mbits >> b & 8u) ? __expf(acc[mb][nf][3]) : 0.f;
                lp[mb][0] += p00 + p01;
                lp[mb][1] += p10 + p11;
                uint32_t h0 = pack_h2(p00, p01);
                uint32_t h1 = pack_h2(p10, p11);
                // one packed fp16 store per row-pair (half the bytes of fp32)
                *(uint32_t*)(pattn + (size_t)(q0 + row)     * S_LEN + kt + col) = h0;
                *(uint32_t*)(pattn + (size_t)(q0 + row + 8) * S_LEN + kt + col) = h1;
                int k2i = wn * 8 + 4 * nf + tig;
                *(uint32_t*)&Ph[row       * PQ2 + k2i] = h0;
                *(uint32_t*)&Ph[(row + 8) * PQ2 + k2i] = h1;
            }
        }

        // ---- V(t) STS (k2-major half2) ----
        {
            int dq = tid & 15;
            #pragma unroll
            for (int i2 = 0; i2 < 2; i2++) {
                int k2 = (tid >> 4) + 16 * i2;
                uint4 h;
                h.x = pack_h2(va[i2].x, vb[i2].x);
                h.y = pack_h2(va[i2].y, vb[i2].y);
                h.z = pack_h2(va[i2].z, vb[i2].z);
                h.w = pack_h2(va[i2].w, vb[i2].w);
                *(uint4*)&Vt[k2 * PKV2 + 4 * dq] = h;
            }
        }

        // ---- K(t+1) LDG (cover = PV phase + next-tile start) ----
        {
            const float* Kn = Kg + (size_t)((kt + NT < S_LEN) ? kt + NT : 0) * D_K;
            #pragma unroll
            for (int i = 0; i < 4; i++) {
                int f = i * THREADS + tid;
                int key = f & 63, kb = f >> 6;
                kreg[i] = *(const float4*)(Kn + (size_t)key * D_K + kb * 4);
            }
        }
        __syncthreads();                     // Ph + Vt visible

        // ---- O += P V (fp16 mma, k16) ----
        #pragma unroll
        for (int j = 0; j < 4; j++) {
            uint32_t a[2][4];
            #pragma unroll
            for (int mb = 0; mb < 2; mb++) {
                int r = wm * 32 + mb * 16 + g;
                a[mb][0] = *(uint32_t*)&Ph[r       * PQ2 + 8 * j + tig];
                a[mb][1] = *(uint32_t*)&Ph[(r + 8) * PQ2 + 8 * j + tig];
                a[mb][2] = *(uint32_t*)&Ph[r       * PQ2 + 8 * j + tig + 4];
                a[mb][3] = *(uint32_t*)&Ph[(r + 8) * PQ2 + 8 * j + tig + 4];
            }
            #pragma unroll
            for (int nf = 0; nf < 2; nf++) {
                int dc = wn * 16 + nf * 8 + g;
                uint32_t b0 = *(uint32_t*)&Vt[(8 * j + tig)     * PKV2 + dc];
                uint32_t b1 = *(uint32_t*)&Vt[(8 * j + tig + 4) * PKV2 + dc];
                #pragma unroll
                for (int mb = 0; mb < 2; mb++)
                    mma_f16(o[mb][nf], a[mb][0], a[mb][1], a[mb][2], a[mb][3], b0, b1);
            }
        }
    }

    // ---- row sums -> l_inv ----
    #pragma unroll
    for (int mb = 0; mb < 2; mb++)
        #pragma unroll
        for (int h = 0; h < 2; h++) {
            float s = lp[mb][h];
            s += __shfl_xor_sync(0xffffffffu, s, 1);
            s += __shfl_xor_sync(0xffffffffu, s, 2);
            lp[mb][h] = s;
        }
    if (tig == 0)
        #pragma unroll
        for (int mb = 0; mb < 2; mb++)
            #pragma unroll
            for (int h = 0; h < 2; h++)
                red[(wm * 32 + mb * 16 + g + h * 8) * 4 + wn] = lp[mb][h];
    __syncthreads();
    if (tid < MT) {
        float li = 1.f / (red[tid * 4] + red[tid * 4 + 1] + red[tid * 4 + 2] + red[tid * 4 + 3]);
        liS[tid] = li;
        g_linv[(size_t)bh * S_LEN + q0 + tid] = li;
    }
    __syncthreads();

    // ---- write context ----
    #pragma unroll
    for (int mb = 0; mb < 2; mb++) {
        int row = wm * 32 + mb * 16 + g;
        float li0 = liS[row], li1 = liS[row + 8];
        #pragma unroll
        for (int nf = 0; nf < 2; nf++) {
            int col = wn * 16 + nf * 8 + 2 * tig;
            *(float2*)(ctx + (size_t)(q0 + row)     * D_K + col) =
                make_float2(o[mb][nf][0] * li0, o[mb][nf][1] * li0);
            *(float2*)(ctx + (size_t)(q0 + row + 8) * D_K + col) =
                make_float2(o[mb][nf][2] * li1, o[mb][nf][3] * li1);
        }
    }

    // ---- produce/consume: expand+normalize one produced fp16 strip -> fp32 out ----
    __threadfence();
    __syncthreads();
    if (tid == 0) {
        int idx = atomicAdd(&g_push, 1);
        asm volatile("st.release.gpu.global.s32 [%0], %1;"
                     :: "l"(g_queue + idx), "r"(myid) : "memory");
        int t = atomicAdd(&g_ticket, 1);
        int s;
        while (true) {
            asm volatile("ld.acquire.gpu.global.s32 %0, [%1];"
                         : "=r"(s) : "l"(g_queue + t) : "memory");
            if (s >= 0) break;
            __nanosleep(64);
        }
        s_strip = s;
    }
    __syncthreads();

    const int sid  = s_strip;
    const int sbh  = sid >> 5;
    const int sq0  = (sid & 31) * MT;
    const half2* sp = g_pattn + ((size_t)sbh * S_LEN + sq0) * (S_LEN / 2);
    float* sattn = attn_base + (size_t)sbh * S_LEN * S_LEN + (size_t)sq0 * S_LEN;
    if (tid < MT) liS[tid] = g_linv[(size_t)sbh * S_LEN + sq0 + tid];
    __syncthreads();

    // 8 fp16 in, 8 fp32 out per iteration
    #pragma unroll 2
    for (int i = tid; i < MT * (S_LEN / 8); i += THREADS) {
        float li = liS[i >> 8];                  // 256 groups of 8 per row
        uint4 raw = *(const uint4*)(sp + (size_t)i * 4);
        float2 f0 = __half22float2(*(half2*)&raw.x);
        float2 f1 = __half22float2(*(half2*)&raw.y);
        float2 f2 = __half22float2(*(half2*)&raw.z);
        float2 f3 = __half22float2(*(half2*)&raw.w);
        float4 o0 = make_float4(f0.x * li, f0.y * li, f1.x * li, f1.y * li);
        float4 o1 = make_float4(f2.x * li, f2.y * li, f3.x * li, f3.y * li);
        *(float4*)(sattn + (size_t)i * 8)     = o0;
        *(float4*)(sattn + (size_t)i * 8 + 4) = o1;
    }
}

extern "C" void kernel_launch(void* const* d_in, const int* in_sizes, int n_in,
                              void* d_out, int out_size) {
    const float* Q    = (const float*)d_in[0];
    const float* K    = (const float*)d_in[1];
    const float* V    = (const float*)d_in[2];
    const int*   mask = (const int*)d_in[3];
    float* out = (float*)d_out;

    void* addr;
    cudaGetSymbolAddress(&addr, g_queue);
    cudaMemsetAsync(addr, 0xFF, sizeof(int) * NBLOCKS);
    cudaGetSymbolAddress(&addr, g_push);
    cudaMemsetAsync(addr, 0, sizeof(int));
    cudaGetSymbolAddress(&addr, g_ticket);
    cudaMemsetAsync(addr, 0, sizeof(int));

    const int smem = (2 * MT * PQ2 + 2 * 32 * PKV2) * 4 + (MT * 4 + MT) * sizeof(float);  // ~38 KB
    cudaFuncSetAttribute(sdpa_fused, cudaFuncAttributeMaxDynamicSharedMemorySize, smem);

    dim3 grid(S_LEN / MT, BH);   // (32, 64)
    sdpa_fused<<<grid, THREADS, smem>>>(Q, K, V, mask, out);
}

// round 12
// speedup vs baseline: 1.4307x; 1.4307x over previous
#include <cuda_runtime.h>
#include <cuda_fp16.h>
#include <cstdint>

#define S_LEN   2048
#define D_K     64
#define BH      64
#define MT      64
#define NT      64
#define PQ2     36    // half2 pad: Qh/Ph reads banks 4g+tig -> conflict-free
#define PKV2    72    // half2 pad: Kt/Vt reads banks 8tig+g -> conflict-free
#define PM      72    // mask smem stride (ints): int2 reads banks 4g+tig -> conflict-free
#define THREADS 256
#define NBLOCKS (BH * (S_LEN / MT))   // 2048

__device__ float g_linv[BH * S_LEN];
__device__ int   g_queue[NBLOCKS];
__device__ int   g_push;
__device__ int   g_ticket;

__device__ __forceinline__ uint32_t pack_h2(float lo, float hi) {
    half2 h = __floats2half2_rn(lo, hi);
    return *(uint32_t*)&h;
}

__device__ __forceinline__ void mma_f16(float c[4],
                                        uint32_t a0, uint32_t a1, uint32_t a2, uint32_t a3,
                                        uint32_t b0, uint32_t b1) {
    asm volatile(
        "mma.sync.aligned.m16n8k16.row.col.f32.f16.f16.f32 "
        "{%0,%1,%2,%3},{%4,%5,%6,%7},{%8,%9},{%0,%1,%2,%3};"
        : "+f"(c[0]), "+f"(c[1]), "+f"(c[2]), "+f"(c[3])
        : "r"(a0), "r"(a1), "r"(a2), "r"(a3), "r"(b0), "r"(b1));
}

__device__ __forceinline__ void cp_async16(uint32_t s, const void* g) {
    asm volatile("cp.async.cg.shared.global [%0], [%1], 16;" :: "r"(s), "l"(g));
}
#define CP_COMMIT() asm volatile("cp.async.commit_group;")
#define CP_WAIT0()  asm volatile("cp.async.wait_group 0;")

// coalesced 64x64 int mask tile -> padded smem
__device__ __forceinline__ void cp_mask(uint32_t dst_base, const int* __restrict__ src,
                                        int tid) {
    #pragma unroll
    for (int i = 0; i < 4; i++) {
        int idx = i * THREADS + tid;
        int row = idx >> 4;
        int c4  = (idx & 15) << 2;
        cp_async16(dst_base + (row * PM + c4) * 4, src + (size_t)row * S_LEN + c4);
    }
}

__global__ __launch_bounds__(THREADS, 3)
void sdpa_fused(const float* __restrict__ Q, const float* __restrict__ K,
                const float* __restrict__ V, const int* __restrict__ mask,
                float* __restrict__ out) {
    extern __shared__ char smraw[];
    half2* Qh  = (half2*)smraw;               // 64 x PQ2  (row, k2)
    half2* Ph  = Qh + MT * PQ2;               // 64 x PQ2  (row, k2)
    half2* Kt  = Ph + MT * PQ2;               // 32 x PKV2 (k2, key)
    half2* Vt  = Kt + 32 * PKV2;              // 32 x PKV2 (k2, d)
    int*   Msm = (int*)(Vt + 32 * PKV2);      // 2 x (64 x PM) mask buffers
    float* red = (float*)(Msm + 2 * 64 * PM); // 64 x 4
    float* liS = red + MT * 4;                // 64
    __shared__ int s_strip;

    const uint32_t base = (uint32_t)__cvta_generic_to_shared(smraw);
    const uint32_t msmA0 = base + (uint32_t)((char*)Msm - smraw);
    const uint32_t msmA[2] = { msmA0, msmA0 + 64 * PM * 4 };

    const int bh  = blockIdx.y;
    const int q0  = blockIdx.x * MT;
    const int myid = blockIdx.y * gridDim.x + blockIdx.x;
    const int tid = threadIdx.x;
    const int lane = tid & 31, wid = tid >> 5;
    const int g = lane >> 2, tig = lane & 3;
    const int wm = wid & 1;                  // 2 warps in M (32 rows each)
    const int wn = wid >> 1;                 // 4 warps in N (16 cols each)

    const float* Qg = Q + ((size_t)bh * S_LEN + q0) * D_K;
    const float* Kg = K + (size_t)bh * S_LEN * D_K;
    const float* Vg = V + (size_t)bh * S_LEN * D_K;
    const int*   Mg = mask + ((size_t)bh * S_LEN + q0) * S_LEN;
    float* ctx  = out + (size_t)bh * S_LEN * D_K;
    float* attn_base = out + (size_t)BH * S_LEN * D_K;
    float* attn = attn_base + (size_t)bh * S_LEN * S_LEN;

    // ---- Q -> fp16 smem (scale 1/8 folded) ----
    {
        const float4* q4 = (const float4*)Qg;
        #pragma unroll
        for (int i = 0; i < 4; i++) {
            int idx = i * THREADS + tid;
            float4 v = q4[idx];
            int row = idx >> 4;
            int c2  = (idx & 15) * 2;
            Qh[row * PQ2 + c2]     = __floats2half2_rn(v.x * 0.125f, v.y * 0.125f);
            Qh[row * PQ2 + c2 + 1] = __floats2half2_rn(v.z * 0.125f, v.w * 0.125f);
        }
    }

    // ---- prefetch mask(0) coalesced + K(0) into registers ----
    cp_mask(msmA[0], Mg, tid);
    CP_COMMIT();
    float4 kreg[4];
    #pragma unroll
    for (int i = 0; i < 4; i++) {
        int f = i * THREADS + tid;
        int key = f & 63, kb = f >> 6;
        kreg[i] = *(const float4*)(Kg + (size_t)key * D_K + kb * 4);
    }

    float o[2][2][4] = {};
    float lp[2][2] = {};
    int par = 0;

    for (int kt = 0; kt < S_LEN; kt += NT, par ^= 1) {
        __syncthreads();                     // prev tile's consumers done

        // ---- K(t) STS from kreg (k2-major half2) ----
        #pragma unroll
        for (int i = 0; i < 4; i++) {
            int f = i * THREADS + tid;
            int key = f & 63, kb = f >> 6;
            Kt[(2 * kb)     * PKV2 + key] = __floats2half2_rn(kreg[i].x, kreg[i].y);
            Kt[(2 * kb + 1) * PKV2 + key] = __floats2half2_rn(kreg[i].z, kreg[i].w);
        }

        // ---- V(t) LDG (consumed after exp; long cover) ----
        float4 va[2], vb[2];
        {
            int dq = tid & 15;
            #pragma unroll
            for (int i2 = 0; i2 < 2; i2++) {
                int k2 = (tid >> 4) + 16 * i2;
                va[i2] = *(const float4*)(Vg + (size_t)(kt + 2 * k2)     * D_K + 4 * dq);
                vb[i2] = *(const float4*)(Vg + (size_t)(kt + 2 * k2 + 1) * D_K + 4 * dq);
            }
        }

        CP_WAIT0();                          // mask(t) copies done (this thread)
        __syncthreads();                     // Kt + Msm[par] visible

        // ---- S = Q K^T (fp16 mma, k16) ----
        float acc[2][2][4] = {};
        #pragma unroll
        for (int j = 0; j < 4; j++) {
            uint32_t a[2][4];
            #pragma unroll
            for (int mb = 0; mb < 2; mb++) {
                int r = wm * 32 + mb * 16 + g;
                a[mb][0] = *(uint32_t*)&Qh[r       * PQ2 + 8 * j + tig];
                a[mb][1] = *(uint32_t*)&Qh[(r + 8) * PQ2 + 8 * j + tig];
                a[mb][2] = *(uint32_t*)&Qh[r       * PQ2 + 8 * j + tig + 4];
                a[mb][3] = *(uint32_t*)&Qh[(r + 8) * PQ2 + 8 * j + tig + 4];
            }
            #pragma unroll
            for (int nf = 0; nf < 2; nf++) {
                int nc = wn * 16 + nf * 8 + g;
                uint32_t b0 = *(uint32_t*)&Kt[(8 * j + tig)     * PKV2 + nc];
                uint32_t b1 = *(uint32_t*)&Kt[(8 * j + tig + 4) * PKV2 + nc];
                #pragma unroll
                for (int mb = 0; mb < 2; mb++)
                    mma_f16(acc[mb][nf], a[mb][0], a[mb][1], a[mb][2], a[mb][3], b0, b1);
            }
        }

        // ---- p = mask*exp(s): mask from smem, attn fp32 store, Ph store, sums ----
        const int* Mt = Msm + par * 64 * PM;
        #pragma unroll
        for (int mb = 0; mb < 2; mb++) {
            int row = wm * 32 + mb * 16 + g;
            #pragma unroll
            for (int nf = 0; nf < 2; nf++) {
                int col = wn * 16 + nf * 8 + 2 * tig;
                int2 m0 = *(const int2*)&Mt[row       * PM + col];
                int2 m1 = *(const int2*)&Mt[(row + 8) * PM + col];
                float p00 = m0.x ? __expf(acc[mb][nf][0]) : 0.f;
                float p01 = m0.y ? __expf(acc[mb][nf][1]) : 0.f;
                float p10 = m1.x ? __expf(acc[mb][nf][2]) : 0.f;
                float p11 = m1.y ? __expf(acc[mb][nf][3]) : 0.f;
                lp[mb][0] += p00 + p01;
                lp[mb][1] += p10 + p11;
                *(float2*)(attn + (size_t)(q0 + row)     * S_LEN + kt + col) = make_float2(p00, p01);
                *(float2*)(attn + (size_t)(q0 + row + 8) * S_LEN + kt + col) = make_float2(p10, p11);
                int k2i = wn * 8 + 4 * nf + tig;
                *(uint32_t*)&Ph[row       * PQ2 + k2i] = pack_h2(p00, p01);
                *(uint32_t*)&Ph[(row + 8) * PQ2 + k2i] = pack_h2(p10, p11);
            }
        }

        // ---- V(t) STS (k2-major half2) ----
        {
            int dq = tid & 15;
            #pragma unroll
            for (int i2 = 0; i2 < 2; i2++) {
                int k2 = (tid >> 4) + 16 * i2;
                uint4 h;
                h.x = pack_h2(va[i2].x, vb[i2].x);
                h.y = pack_h2(va[i2].y, vb[i2].y);
                h.z = pack_h2(va[i2].z, vb[i2].z);
                h.w = pack_h2(va[i2].w, vb[i2].w);
                *(uint4*)&Vt[k2 * PKV2 + 4 * dq] = h;
            }
        }

        // ---- K(t+1) LDG + mask(t+1) cp.async (cover = PV + next-tile start) ----
        {
            int ktn = (kt + NT < S_LEN) ? kt + NT : 0;
            const float* Kn = Kg + (size_t)ktn * D_K;
            #pragma unroll
            for (int i = 0; i < 4; i++) {
                int f = i * THREADS + tid;
                int key = f & 63, kb = f >> 6;
                kreg[i] = *(const float4*)(Kn + (size_t)key * D_K + kb * 4);
            }
            cp_mask(msmA[par ^ 1], Mg + ktn, tid);
            CP_COMMIT();
        }
        __syncthreads();                     // Ph + Vt visible

        // ---- O += P V (fp16 mma, k16) ----
        #pragma unroll
        for (int j = 0; j < 4; j++) {
            uint32_t a[2][4];
            #pragma unroll
            for (int mb = 0; mb < 2; mb++) {
                int r = wm * 32 + mb * 16 + g;
                a[mb][0] = *(uint32_t*)&Ph[r       * PQ2 + 8 * j + tig];
                a[mb][1] = *(uint32_t*)&Ph[(r + 8) * PQ2 + 8 * j + tig];
                a[mb][2] = *(uint32_t*)&Ph[r       * PQ2 + 8 * j + tig + 4];
                a[mb][3] = *(uint32_t*)&Ph[(r + 8) * PQ2 + 8 * j + tig + 4];
            }
            #pragma unroll
            for (int nf = 0; nf < 2; nf++) {
                int dc = wn * 16 + nf * 8 + g;
                uint32_t b0 = *(uint32_t*)&Vt[(8 * j + tig)     * PKV2 + dc];
                uint32_t b1 = *(uint32_t*)&Vt[(8 * j + tig + 4) * PKV2 + dc];
                #pragma unroll
                for (int mb = 0; mb < 2; mb++)
                    mma_f16(o[mb][nf], a[mb][0], a[mb][1], a[mb][2], a[mb][3], b0, b1);
            }
        }
    }

    // ---- row sums -> l_inv ----
    #pragma unroll
    for (int mb = 0; mb < 2; mb++)
        #pragma unroll
        for (int h = 0; h < 2; h++) {
            float s = lp[mb][h];
            s += __shfl_xor_sync(0xffffffffu, s, 1);
            s += __shfl_xor_sync(0xffffffffu, s, 2);
            lp[mb][h] = s;
        }
    if (tig == 0)
        #pragma unroll
        for (int mb = 0; mb < 2; mb++)
            #pragma unroll
            for (int h = 0; h < 2; h++)
                red[(wm * 32 + mb * 16 + g + h * 8) * 4 + wn] = lp[mb][h];
    __syncthreads();
    if (tid < MT) {
        float li = 1.f / (red[tid * 4] + red[tid * 4 + 1] + red[tid * 4 + 2] + red[tid * 4 + 3]);
        liS[tid] = li;
        g_linv[(size_t)bh * S_LEN + q0 + tid] = li;
    }
    __syncthreads();

    // ---- write context ----
    #pragma unroll
    for (int mb = 0; mb < 2; mb++) {
        int row = wm * 32 + mb * 16 + g;
        float li0 = liS[row], li1 = liS[row + 8];
        #pragma unroll
        for (int nf = 0; nf < 2; nf++) {
            int col = wn * 16 + nf * 8 + 2 * tig;
            *(float2*)(ctx + (size_t)(q0 + row)     * D_K + col) =
                make_float2(o[mb][nf][0] * li0, o[mb][nf][1] * li0);
            *(float2*)(ctx + (size_t)(q0 + row + 8) * D_K + col) =
                make_float2(o[mb][nf][2] * li1, o[mb][nf][3] * li1);
        }
    }

    // ---- produce/consume: normalize one already-produced strip ----
    __threadfence();
    __syncthreads();
    if (tid == 0) {
        int idx = atomicAdd(&g_push, 1);
        asm volatile("st.release.gpu.global.s32 [%0], %1;"
                     :: "l"(g_queue + idx), "r"(myid) : "memory");
        int t = atomicAdd(&g_ticket, 1);
        int s;
        while (true) {
            asm volatile("ld.acquire.gpu.global.s32 %0, [%1];"
                         : "=r"(s) : "l"(g_queue + t) : "memory");
            if (s >= 0) break;
            __nanosleep(64);
        }
        s_strip = s;
    }
    __syncthreads();

    const int sid  = s_strip;
    const int sbh  = sid >> 5;
    const int sq0  = (sid & 31) * MT;
    float* sattn = attn_base + (size_t)sbh * S_LEN * S_LEN + (size_t)sq0 * S_LEN;
    if (tid < MT) liS[tid] = g_linv[(size_t)sbh * S_LEN + sq0 + tid];
    __syncthreads();

    #pragma unroll 4
    for (int i = tid; i < MT * (S_LEN / 4); i += THREADS) {
        float li = liS[i >> 9];
        float4* p = (float4*)sattn + i;
        float4 v = *p;
        v.x *= li; v.y *= li; v.z *= li; v.w *= li;
        *p = v;
    }
}

extern "C" void kernel_launch(void* const* d_in, const int* in_sizes, int n_in,
                              void* d_out, int out_size) {
    const float* Q    = (const float*)d_in[0];
    const float* K    = (const float*)d_in[1];
    const float* V    = (const float*)d_in[2];
    const int*   mask = (const int*)d_in[3];
    float* out = (float*)d_out;

    void* addr;
    cudaGetSymbolAddress(&addr, g_queue);
    cudaMemsetAsync(addr, 0xFF, sizeof(int) * NBLOCKS);
    cudaGetSymbolAddress(&addr, g_push);
    cudaMemsetAsync(addr, 0, sizeof(int));
    cudaGetSymbolAddress(&addr, g_ticket);
    cudaMemsetAsync(addr, 0, sizeof(int));

    const int smem = (2 * MT * PQ2 + 2 * 32 * PKV2) * 4      // Qh, Ph, Kt, Vt
                   + 2 * 64 * PM * 4                          // mask double buffer
                   + (MT * 4 + MT) * sizeof(float);           // red + liS  (~75 KB)
    cudaFuncSetAttribute(sdpa_fused, cudaFuncAttributeMaxDynamicSharedMemorySize, smem);

    dim3 grid(S_LEN / MT, BH);   // (32, 64)
    sdpa_fused<<<grid, THREADS, smem>>>(Q, K, V, mask, out);
}